// round 1
// baseline (speedup 1.0000x reference)
#include <cuda_runtime.h>
#include <math.h>

// ---- problem constants ----
#define BSX 4096   // B*S
#define BB  2
#define SEQ 2048
#define EMB 768
#define TT  128
#define NH  12
#define DHD 64
#define FF  3072
#define KNN 16

// ---- scratch (device globals; no allocation allowed) ----
__device__ float g_hn[BSX * EMB];
__device__ float g_x[BSX * EMB];          // LN1(h)
__device__ float g_topo[BSX * TT];
__device__ float g_comb[BSX * TT];
__device__ float g_tmp256[BSX * 256];
__device__ float g_t[BSX * TT];
__device__ float g_pf[BSX * TT];
__device__ float g_q[BSX * EMB];
__device__ float g_k[BSX * EMB];
__device__ float g_v[BSX * EMB];
__device__ float g_ctx[BSX * EMB];
__device__ float g_cat[BSX * (EMB + TT)];
__device__ float g_gl[BSX * EMB];
__device__ float g_h1[BSX * EMB];
__device__ float g_y[BSX * EMB];
__device__ float g_ff[(long long)BSX * FF];
__device__ float g_knw[BSX * KNN];
__device__ int   g_kni[BSX * KNN];
// scores / distance scratch: [B][H][S][S] = 402 MB (distance matrix reuses front)
__device__ float g_scores[(long long)BB * NH * SEQ * SEQ];

// ============================================================================
// Generic tiled GEMM: C[M,N] = act(A[M,K] @ op(B) + bias) (+ res)
// op(B) = B[K,N] (TRANSB=0) or B[N,K]^T (TRANSB=1)
// ACT: 0=none, 1=relu, 2=gelu(tanh)
// Batched via grid.z with two-level offsets: off = (z%zdiv)*s1 + (z/zdiv)*s2
// Requirements (all satisfied here): M%64==0, N%64==0, K%16==0, ld%4==0
// ============================================================================
template<int TRANSB, int ACT>
__global__ void gemm_k(const float* __restrict__ A, const float* __restrict__ B,
                       float* __restrict__ C, const float* __restrict__ bias,
                       const float* __restrict__ res,
                       int M, int N, int K, int lda, int ldb, int ldc,
                       int zdiv, long long sA1, long long sA2,
                       long long sB1, long long sB2,
                       long long sC1, long long sC2)
{
    __shared__ float As[16][64];
    __shared__ float Bs[16][64];

    int z = blockIdx.z;
    long long zm = z % zdiv, zd = z / zdiv;
    A += zm * sA1 + zd * sA2;
    B += zm * sB1 + zd * sB2;
    long long co = zm * sC1 + zd * sC2;
    C += co;
    if (res) res += co;

    int t  = threadIdx.x;                 // 256 threads
    int bm = blockIdx.y * 64, bn = blockIdx.x * 64;
    int lrow = t >> 2;                    // 0..63
    int lkq  = (t & 3) * 4;               // 0,4,8,12
    int brow = t >> 4;                    // 0..15
    int bnq  = (t & 15) * 4;              // 0..60
    int ty = (t >> 4) * 4, tx = (t & 15) * 4;

    float acc[4][4];
    #pragma unroll
    for (int i = 0; i < 4; i++)
        #pragma unroll
        for (int j = 0; j < 4; j++) acc[i][j] = 0.f;

    for (int k0 = 0; k0 < K; k0 += 16) {
        float4 av = *(const float4*)(A + (long long)(bm + lrow) * lda + k0 + lkq);
        As[lkq + 0][lrow] = av.x;
        As[lkq + 1][lrow] = av.y;
        As[lkq + 2][lrow] = av.z;
        As[lkq + 3][lrow] = av.w;
        if (TRANSB) {
            float4 bv = *(const float4*)(B + (long long)(bn + lrow) * ldb + k0 + lkq);
            Bs[lkq + 0][lrow] = bv.x;
            Bs[lkq + 1][lrow] = bv.y;
            Bs[lkq + 2][lrow] = bv.z;
            Bs[lkq + 3][lrow] = bv.w;
        } else {
            float4 bv = *(const float4*)(B + (long long)(k0 + brow) * ldb + bn + bnq);
            *(float4*)&Bs[brow][bnq] = bv;
        }
        __syncthreads();
        #pragma unroll
        for (int kk = 0; kk < 16; kk++) {
            float4 a4 = *(const float4*)&As[kk][ty];
            float4 b4 = *(const float4*)&Bs[kk][tx];
            float aa[4] = {a4.x, a4.y, a4.z, a4.w};
            float bb[4] = {b4.x, b4.y, b4.z, b4.w};
            #pragma unroll
            for (int i = 0; i < 4; i++)
                #pragma unroll
                for (int j = 0; j < 4; j++)
                    acc[i][j] += aa[i] * bb[j];
        }
        __syncthreads();
    }

    #pragma unroll
    for (int i = 0; i < 4; i++) {
        int m = bm + ty + i;
        #pragma unroll
        for (int j = 0; j < 4; j++) {
            int n = bn + tx + j;
            float v = acc[i][j];
            if (bias) v += bias[n];
            if (ACT == 1) v = fmaxf(v, 0.f);
            if (ACT == 2) {
                float u = v;
                v = 0.5f * u * (1.f + tanhf(0.7978845608028654f * (u + 0.044715f * u * u * u)));
            }
            long long off = (long long)m * ldc + n;
            if (res) v += res[off];
            C[off] = v;
        }
    }
}

// ---- row L2 normalize: hn = h / (||h|| + 1e-8) ----
__global__ void l2norm_k(const float* __restrict__ h)
{
    int row = blockIdx.x, t = threadIdx.x;
    const float* x = h + (long long)row * EMB;
    __shared__ float red[256];
    float s = 0.f;
    for (int i = t; i < EMB; i += 256) { float v = x[i]; s += v * v; }
    red[t] = s; __syncthreads();
    for (int st = 128; st > 0; st >>= 1) { if (t < st) red[t] += red[t + st]; __syncthreads(); }
    float inv = 1.f / (sqrtf(red[0]) + 1e-8f);
    for (int i = t; i < EMB; i += 256) g_hn[(long long)row * EMB + i] = x[i] * inv;
}

// ---- layernorm (two-pass; eps 1e-6) ----
__global__ void ln_k(const float* __restrict__ x, float* __restrict__ o,
                     const float* __restrict__ gma, const float* __restrict__ bta, int D)
{
    int row = blockIdx.x, t = threadIdx.x;
    const float* xr = x + (long long)row * D;
    __shared__ float red[256];
    __shared__ float s_mu, s_ri;
    float s = 0.f;
    for (int i = t; i < D; i += 256) s += xr[i];
    red[t] = s; __syncthreads();
    for (int st = 128; st > 0; st >>= 1) { if (t < st) red[t] += red[t + st]; __syncthreads(); }
    if (t == 0) s_mu = red[0] / D;
    __syncthreads();
    float mu = s_mu;
    float v = 0.f;
    for (int i = t; i < D; i += 256) { float d = xr[i] - mu; v += d * d; }
    __syncthreads();
    red[t] = v; __syncthreads();
    for (int st = 128; st > 0; st >>= 1) { if (t < st) red[t] += red[t + st]; __syncthreads(); }
    if (t == 0) s_ri = rsqrtf(red[0] / D + 1e-6f);
    __syncthreads();
    float ri = s_ri;
    for (int i = t; i < D; i += 256)
        o[(long long)row * D + i] = (xr[i] - mu) * ri * gma[i] + bta[i];
}

// ---- k-NN: 16 iterated argmins over a shared-memory distance row ----
__global__ void knn_k()
{
    int row = blockIdx.x;             // global row b*S+i
    int b = row / SEQ, i = row % SEQ;
    const float* dr = g_scores + (long long)row * SEQ; // dot products [b][i][j]
    __shared__ float sd[SEQ];
    __shared__ float rv[256];
    __shared__ int   ri[256];
    __shared__ float knd[KNN];
    __shared__ int   sel[KNN];
    int t = threadIdx.x;
    for (int j = t; j < SEQ; j += 256)
        sd[j] = (j == i) ? 1e9f : (1.f - dr[j]);
    __syncthreads();
    for (int it = 0; it < KNN; it++) {
        float bv = 1e30f; int bi = 0x7fffffff;
        for (int j = t; j < SEQ; j += 256) {
            float d = sd[j];
            if (d < bv || (d == bv && j < bi)) { bv = d; bi = j; }
        }
        rv[t] = bv; ri[t] = bi; __syncthreads();
        for (int st = 128; st > 0; st >>= 1) {
            if (t < st) {
                float ov = rv[t + st]; int oi = ri[t + st];
                if (ov < rv[t] || (ov == rv[t] && oi < ri[t])) { rv[t] = ov; ri[t] = oi; }
            }
            __syncthreads();
        }
        if (t == 0) { knd[it] = rv[0]; sel[it] = ri[0]; sd[ri[0]] = 1e9f; }
        __syncthreads();
    }
    if (t == 0) {
        // softmax(-nd); knd is sorted ascending, so max(-nd) = -knd[0]
        float w[KNN], sum = 0.f;
        for (int k2 = 0; k2 < KNN; k2++) { w[k2] = expf(knd[0] - knd[k2]); sum += w[k2]; }
        float inv = 1.f / sum;
        for (int k2 = 0; k2 < KNN; k2++) {
            g_knw[row * KNN + k2] = w[k2] * inv;
            g_kni[row * KNN + k2] = b * SEQ + sel[k2];
        }
    }
}

// ---- combined = topo + sum_k w_k * topo[nbr_k] ----
__global__ void combine_k()
{
    int row = blockIdx.x, t = threadIdx.x; // 128 threads
    float acc = g_topo[(long long)row * TT + t];
    #pragma unroll
    for (int k2 = 0; k2 < KNN; k2++)
        acc += g_knw[row * KNN + k2] * g_topo[(long long)g_kni[row * KNN + k2] * TT + t];
    g_comb[(long long)row * TT + t] = acc;
}

// ---- attention softmax over keys (scale 1/8, mask==0 -> -10000) ----
__global__ void attn_softmax_k(const int* __restrict__ mask)
{
    int q = blockIdx.x, z = blockIdx.y;
    int b = z / NH;
    float* row = g_scores + (long long)z * SEQ * SEQ + (long long)q * SEQ;
    const int* mrow = mask + b * SEQ;
    int t = threadIdx.x;
    __shared__ float red[256];
    __shared__ float s_mx, s_sum;
    float mx = -1e30f;
    for (int k2 = t; k2 < SEQ; k2 += 256) {
        float v = row[k2] * 0.125f;
        if (mrow[k2] == 0) v = -10000.f;
        row[k2] = v;
        mx = fmaxf(mx, v);
    }
    red[t] = mx; __syncthreads();
    for (int st = 128; st > 0; st >>= 1) { if (t < st) red[t] = fmaxf(red[t], red[t + st]); __syncthreads(); }
    if (t == 0) s_mx = red[0];
    __syncthreads();
    mx = s_mx;
    float sum = 0.f;
    for (int k2 = t; k2 < SEQ; k2 += 256) sum += expf(row[k2] - mx);
    __syncthreads();
    red[t] = sum; __syncthreads();
    for (int st = 128; st > 0; st >>= 1) { if (t < st) red[t] += red[t + st]; __syncthreads(); }
    if (t == 0) s_sum = red[0];
    __syncthreads();
    float inv = 1.f / s_sum;
    for (int k2 = t; k2 < SEQ; k2 += 256) row[k2] = expf(row[k2] - mx) * inv;
}

// ---- concat [ctx, pf] -> cat ----
__global__ void concat_k()
{
    long long idx = (long long)blockIdx.x * 256 + threadIdx.x;
    if (idx >= (long long)BSX * (EMB + TT)) return;
    int row = (int)(idx / (EMB + TT));
    int c   = (int)(idx % (EMB + TT));
    g_cat[idx] = (c < EMB) ? g_ctx[(long long)row * EMB + c]
                           : g_pf[(long long)row * TT + (c - EMB)];
}

// ---- gate = sigmoid(gl); ctx = gate*ctx + (1-gate)*x ----
__global__ void gatemix_k()
{
    long long idx = (long long)blockIdx.x * 256 + threadIdx.x;
    if (idx >= (long long)BSX * EMB) return;
    float g = 1.f / (1.f + expf(-g_gl[idx]));
    g_ctx[idx] = g * g_ctx[idx] + (1.f - g) * g_x[idx];
}

// ============================================================================
extern "C" void kernel_launch(void* const* d_in, const int* in_sizes, int n_in,
                              void* d_out, int out_size)
{
    const float* h      = (const float*)d_in[0];
    const int*   mask   = (const int*)  d_in[1];
    const float* W_topo = (const float*)d_in[2];
    const float* b_topo = (const float*)d_in[3];
    const float* W_m1   = (const float*)d_in[4];
    const float* b_m1   = (const float*)d_in[5];
    const float* W_m2   = (const float*)d_in[6];
    const float* b_m2   = (const float*)d_in[7];
    const float* ln_t_s = (const float*)d_in[8];
    const float* ln_t_b = (const float*)d_in[9];
    const float* W_p1   = (const float*)d_in[10];
    const float* b_p1   = (const float*)d_in[11];
    const float* W_p2   = (const float*)d_in[12];
    const float* b_p2   = (const float*)d_in[13];
    const float* ln1_s  = (const float*)d_in[14];
    const float* ln1_b  = (const float*)d_in[15];
    const float* Wq     = (const float*)d_in[16];
    const float* Wk     = (const float*)d_in[17];
    const float* Wv     = (const float*)d_in[18];
    const float* W_gate = (const float*)d_in[19];
    const float* b_gate = (const float*)d_in[20];
    const float* W_o    = (const float*)d_in[21];
    const float* b_o    = (const float*)d_in[22];
    const float* ln2_s  = (const float*)d_in[23];
    const float* ln2_b  = (const float*)d_in[24];
    const float* W_f1   = (const float*)d_in[25];
    const float* b_f1   = (const float*)d_in[26];
    const float* W_f2   = (const float*)d_in[27];
    const float* b_f2   = (const float*)d_in[28];
    float* out = (float*)d_out;

    float *hn, *x, *topo, *comb, *tmp256, *tt, *pf, *q, *k, *v, *ctx, *cat, *gl, *h1, *y, *ff, *scores;
    cudaGetSymbolAddress((void**)&hn,     g_hn);
    cudaGetSymbolAddress((void**)&x,      g_x);
    cudaGetSymbolAddress((void**)&topo,   g_topo);
    cudaGetSymbolAddress((void**)&comb,   g_comb);
    cudaGetSymbolAddress((void**)&tmp256, g_tmp256);
    cudaGetSymbolAddress((void**)&tt,     g_t);
    cudaGetSymbolAddress((void**)&pf,     g_pf);
    cudaGetSymbolAddress((void**)&q,      g_q);
    cudaGetSymbolAddress((void**)&k,      g_k);
    cudaGetSymbolAddress((void**)&v,      g_v);
    cudaGetSymbolAddress((void**)&ctx,    g_ctx);
    cudaGetSymbolAddress((void**)&cat,    g_cat);
    cudaGetSymbolAddress((void**)&gl,     g_gl);
    cudaGetSymbolAddress((void**)&h1,     g_h1);
    cudaGetSymbolAddress((void**)&y,      g_y);
    cudaGetSymbolAddress((void**)&ff,     g_ff);
    cudaGetSymbolAddress((void**)&scores, g_scores);

    const long long SE  = (long long)SEQ * EMB;
    const long long SS  = (long long)SEQ * SEQ;
    const long long HSS = (long long)NH * SS;

    // 1. hn = normalize(h); x = LN1(h)
    l2norm_k<<<BSX, 256>>>(h);
    ln_k<<<BSX, 256>>>(h, x, ln1_s, ln1_b, EMB);

    // 2. topo = h @ W_topo + b_topo
    gemm_k<0, 0><<<dim3(TT / 64, BSX / 64, 1), 256>>>(h, W_topo, topo, b_topo, nullptr,
        BSX, TT, EMB, EMB, TT, TT, 1, 0, 0, 0, 0, 0, 0);

    // 3. dot[b] = hn[b] @ hn[b]^T  (into scores scratch; reused before attention)
    gemm_k<1, 0><<<dim3(SEQ / 64, SEQ / 64, 2), 256>>>(hn, hn, scores, nullptr, nullptr,
        SEQ, SEQ, EMB, EMB, EMB, SEQ, 2, SE, 0, SE, 0, SS, 0);

    // 4. per-row top-16 NN + softmax weights; combine
    knn_k<<<BSX, 256>>>();
    combine_k<<<BSX, TT>>>();

    // 5. topo MLP: relu(comb @ W_m1 + b_m1) @ W_m2 + b_m2 ; LN_t
    gemm_k<0, 1><<<dim3(256 / 64, BSX / 64, 1), 256>>>(comb, W_m1, tmp256, b_m1, nullptr,
        BSX, 256, TT, TT, 256, 256, 1, 0, 0, 0, 0, 0, 0);
    gemm_k<0, 0><<<dim3(TT / 64, BSX / 64, 1), 256>>>(tmp256, W_m2, tt, b_m2, nullptr,
        BSX, TT, 256, 256, TT, TT, 1, 0, 0, 0, 0, 0, 0);
    ln_k<<<BSX, 256>>>(tt, tt, ln_t_s, ln_t_b, TT);

    // 6. pf = relu(t @ W_p1 + b_p1) @ W_p2 + b_p2
    gemm_k<0, 1><<<dim3(TT / 64, BSX / 64, 1), 256>>>(tt, W_p1, tmp256, b_p1, nullptr,
        BSX, TT, TT, TT, TT, TT, 1, 0, 0, 0, 0, 0, 0);
    gemm_k<0, 0><<<dim3(TT / 64, BSX / 64, 1), 256>>>(tmp256, W_p2, pf, b_p2, nullptr,
        BSX, TT, TT, TT, TT, TT, 1, 0, 0, 0, 0, 0, 0);

    // 7. q/k/v = x @ W{q,k,v}
    gemm_k<0, 0><<<dim3(EMB / 64, BSX / 64, 1), 256>>>(x, Wq, q, nullptr, nullptr,
        BSX, EMB, EMB, EMB, EMB, EMB, 1, 0, 0, 0, 0, 0, 0);
    gemm_k<0, 0><<<dim3(EMB / 64, BSX / 64, 1), 256>>>(x, Wk, k, nullptr, nullptr,
        BSX, EMB, EMB, EMB, EMB, EMB, 1, 0, 0, 0, 0, 0, 0);
    gemm_k<0, 0><<<dim3(EMB / 64, BSX / 64, 1), 256>>>(x, Wv, v, nullptr, nullptr,
        BSX, EMB, EMB, EMB, EMB, EMB, 1, 0, 0, 0, 0, 0, 0);

    // 8. scores[b,h] = q[b,:,h] @ k[b,:,h]^T   (z = b*12 + h)
    gemm_k<1, 0><<<dim3(SEQ / 64, SEQ / 64, BB * NH), 256>>>(q, k, scores, nullptr, nullptr,
        SEQ, SEQ, DHD, EMB, EMB, SEQ,
        NH, DHD, SE, DHD, SE, SS, HSS);

    // 9. softmax (scale + mask folded in)
    attn_softmax_k<<<dim3(SEQ, BB * NH), 256>>>(mask);

    // 10. ctx[b,:,h] = probs[b,h] @ v[b,:,h]
    gemm_k<0, 0><<<dim3(DHD / 64, SEQ / 64, BB * NH), 256>>>(scores, v, ctx, nullptr, nullptr,
        SEQ, DHD, SEQ, SEQ, EMB, EMB,
        NH, SS, HSS, DHD, SE, DHD, SE);

    // 11. gate = sigmoid([ctx, pf] @ W_gate + b_gate); ctx = gate*ctx + (1-gate)*x
    {
        long long n = (long long)BSX * (EMB + TT);
        concat_k<<<(unsigned)((n + 255) / 256), 256>>>();
    }
    gemm_k<0, 0><<<dim3(EMB / 64, BSX / 64, 1), 256>>>(cat, W_gate, gl, b_gate, nullptr,
        BSX, EMB, EMB + TT, EMB + TT, EMB, EMB, 1, 0, 0, 0, 0, 0, 0);
    {
        long long n = (long long)BSX * EMB;
        gatemix_k<<<(unsigned)((n + 255) / 256), 256>>>();
    }

    // 12. h1 = h + ctx @ W_o + b_o
    gemm_k<0, 0><<<dim3(EMB / 64, BSX / 64, 1), 256>>>(ctx, W_o, h1, b_o, h,
        BSX, EMB, EMB, EMB, EMB, EMB, 1, 0, 0, 0, 0, 0, 0);

    // 13. FFN: y = LN2(h1); out = h1 + gelu(y@W_f1+b_f1) @ W_f2 + b_f2
    ln_k<<<BSX, 256>>>(h1, y, ln2_s, ln2_b, EMB);
    gemm_k<0, 2><<<dim3(FF / 64, BSX / 64, 1), 256>>>(y, W_f1, ff, b_f1, nullptr,
        BSX, FF, EMB, EMB, FF, FF, 1, 0, 0, 0, 0, 0, 0);
    gemm_k<0, 0><<<dim3(EMB / 64, BSX / 64, 1), 256>>>(ff, W_f2, out, b_f2, h1,
        BSX, EMB, FF, FF, EMB, EMB, 1, 0, 0, 0, 0, 0, 0);
}

// round 2
// speedup vs baseline: 2.2749x; 2.2749x over previous
#include <cuda_runtime.h>
#include <math.h>
#include <stdint.h>

// ---- problem constants ----
#define BSX 4096   // B*S
#define BB  2
#define SEQ 2048
#define EMB 768
#define TT  128
#define NH  12
#define DHD 64
#define FF  3072
#define KNN 16

// ---- scratch (device globals; no allocation allowed) ----
__device__ float g_hn[BSX * EMB];
__device__ float g_x[BSX * EMB];          // LN1(h)
__device__ float g_topo[BSX * TT];
__device__ float g_comb[BSX * TT];
__device__ float g_tmp256[BSX * 256];
__device__ float g_t[BSX * TT];
__device__ float g_pf[BSX * TT];
__device__ float g_q[BSX * EMB];
__device__ float g_k[BSX * EMB];
__device__ float g_v[BSX * EMB];
__device__ float g_ctx[BSX * EMB];
__device__ float g_cat[BSX * (EMB + TT)];
__device__ float g_gl[BSX * EMB];
__device__ float g_h1[BSX * EMB];
__device__ float g_y[BSX * EMB];
__device__ float g_ff[(long long)BSX * FF];
__device__ float g_knw[BSX * KNN];
__device__ int   g_kni[BSX * KNN];
// scores / distance scratch: [B][H][S][S] = 402 MB (distance matrix reuses front)
__device__ float g_scores[(long long)BB * NH * SEQ * SEQ];

__device__ __forceinline__ uint32_t f2tf(float x) {
    uint32_t u;
    asm("cvt.rna.tf32.f32 %0, %1;" : "=r"(u) : "f"(x));
    return u;
}

__device__ __forceinline__ void mma_tf32(float* c, const uint32_t* a, uint32_t b0, uint32_t b1) {
    asm volatile(
        "mma.sync.aligned.m16n8k8.row.col.f32.tf32.tf32.f32 "
        "{%0,%1,%2,%3},{%4,%5,%6,%7},{%8,%9},{%0,%1,%2,%3};"
        : "+f"(c[0]), "+f"(c[1]), "+f"(c[2]), "+f"(c[3])
        : "r"(a[0]), "r"(a[1]), "r"(a[2]), "r"(a[3]), "r"(b0), "r"(b1));
}

// ============================================================================
// Tensor-core tf32 GEMM: C[M,N] = act(A[M,K] @ op(B) + bias) (+ res)
// op(B) = B[K,N] (TRANSB=0) or B[N,K]^T (TRANSB=1)
// ACT: 0=none, 1=relu, 2=gelu(tanh). Block tile 128 x TN, 256 threads.
// Requirements: M%128==0, N%TN==0, K%16==0, all lds %4==0, TN in {64,128}.
// Batched via grid.z two-level offsets.
// ============================================================================
template<int TRANSB, int ACT, int TN>
__global__ void __launch_bounds__(256) tgemm(
    const float* __restrict__ A, const float* __restrict__ B,
    float* __restrict__ C, const float* __restrict__ bias,
    const float* __restrict__ res,
    int M, int N, int K, int lda, int ldb, int ldc,
    int zdiv, long long sA1, long long sA2,
    long long sB1, long long sB2,
    long long sC1, long long sC2)
{
    constexpr int NT    = TN / 16;              // n8-tiles per warp
    constexpr int BROWS = TRANSB ? TN : 16;
    constexpr int BCOLS = TRANSB ? 20 : (TN + 8);
    constexpr int BITER = TN / 64;              // float4 loads per thread for B

    __shared__ uint32_t As[2][128][20];
    __shared__ uint32_t Bs[2][BROWS][BCOLS];

    int z = blockIdx.z;
    long long zm = z % zdiv, zd = z / zdiv;
    A += zm * sA1 + zd * sA2;
    B += zm * sB1 + zd * sB2;
    long long co = zm * sC1 + zd * sC2;
    C += co;
    if (res) res += co;

    const int t    = threadIdx.x;
    const int lane = t & 31;
    const int wid  = t >> 5;
    const int lr   = lane >> 2;   // groupID
    const int lc   = lane & 3;    // threadID_in_group
    const int wm   = (wid & 3) * 32;
    const int wn   = (wid >> 2) * (TN / 2);
    const int bm   = blockIdx.y * 128;
    const int bn   = blockIdx.x * TN;

    float acc[2][NT][4];
    #pragma unroll
    for (int mt = 0; mt < 2; mt++)
        #pragma unroll
        for (int nt = 0; nt < NT; nt++)
            #pragma unroll
            for (int i = 0; i < 4; i++) acc[mt][nt][i] = 0.f;

    float4 pa[2], pb[2];

    // global -> regs
    auto gload = [&](int k0) {
        #pragma unroll
        for (int i = 0; i < 2; i++) {
            int flat = t + i * 256;
            int row = flat >> 2, kq = (flat & 3) << 2;
            pa[i] = *(const float4*)(A + (long long)(bm + row) * lda + k0 + kq);
        }
        if (TRANSB) {
            #pragma unroll
            for (int i = 0; i < BITER; i++) {
                int flat = t + i * 256;
                int row = flat >> 2, kq = (flat & 3) << 2;
                pb[i] = *(const float4*)(B + (long long)(bn + row) * ldb + k0 + kq);
            }
        } else {
            #pragma unroll
            for (int i = 0; i < BITER; i++) {
                int flat = t + i * 256;
                int krow = flat / (TN / 4), n4 = (flat % (TN / 4)) << 2;
                pb[i] = *(const float4*)(B + (long long)(k0 + krow) * ldb + bn + n4);
            }
        }
    };

    // regs -> shared (tf32)
    auto sstore = [&](int buf) {
        #pragma unroll
        for (int i = 0; i < 2; i++) {
            int flat = t + i * 256;
            int row = flat >> 2, kq = (flat & 3) << 2;
            uint4 u = {f2tf(pa[i].x), f2tf(pa[i].y), f2tf(pa[i].z), f2tf(pa[i].w)};
            *(uint4*)&As[buf][row][kq] = u;
        }
        if (TRANSB) {
            #pragma unroll
            for (int i = 0; i < BITER; i++) {
                int flat = t + i * 256;
                int row = flat >> 2, kq = (flat & 3) << 2;
                uint4 u = {f2tf(pb[i].x), f2tf(pb[i].y), f2tf(pb[i].z), f2tf(pb[i].w)};
                *(uint4*)&Bs[buf][row][kq] = u;
            }
        } else {
            #pragma unroll
            for (int i = 0; i < BITER; i++) {
                int flat = t + i * 256;
                int krow = flat / (TN / 4), n4 = (flat % (TN / 4)) << 2;
                uint4 u = {f2tf(pb[i].x), f2tf(pb[i].y), f2tf(pb[i].z), f2tf(pb[i].w)};
                *(uint4*)&Bs[buf][krow][n4] = u;
            }
        }
    };

    gload(0);
    sstore(0);
    __syncthreads();

    const int iters = K >> 4;
    for (int kb = 0; kb < iters; kb++) {
        int cur = kb & 1;
        bool nxt = (kb + 1) < iters;
        if (nxt) gload((kb + 1) << 4);

        #pragma unroll
        for (int ks = 0; ks < 16; ks += 8) {
            uint32_t af[2][4];
            #pragma unroll
            for (int mt = 0; mt < 2; mt++) {
                int m = wm + mt * 16 + lr;
                af[mt][0] = As[cur][m][ks + lc];
                af[mt][1] = As[cur][m + 8][ks + lc];
                af[mt][2] = As[cur][m][ks + lc + 4];
                af[mt][3] = As[cur][m + 8][ks + lc + 4];
            }
            #pragma unroll
            for (int nt = 0; nt < NT; nt++) {
                int n = wn + nt * 8 + lr;
                uint32_t b0, b1;
                if (TRANSB) {
                    b0 = Bs[cur][n][ks + lc];
                    b1 = Bs[cur][n][ks + lc + 4];
                } else {
                    b0 = Bs[cur][ks + lc][n];
                    b1 = Bs[cur][ks + lc + 4][n];
                }
                #pragma unroll
                for (int mt = 0; mt < 2; mt++)
                    mma_tf32(acc[mt][nt], af[mt], b0, b1);
            }
        }

        if (nxt) {
            sstore(cur ^ 1);
            __syncthreads();
        }
    }

    // epilogue
    #pragma unroll
    for (int mt = 0; mt < 2; mt++) {
        #pragma unroll
        for (int nt = 0; nt < NT; nt++) {
            int mrow = bm + wm + mt * 16 + lr;
            int ncol = bn + wn + nt * 8 + 2 * lc;
            #pragma unroll
            for (int half = 0; half < 2; half++) {
                int m = mrow + half * 8;
                float v0 = acc[mt][nt][half * 2 + 0];
                float v1 = acc[mt][nt][half * 2 + 1];
                if (bias) { v0 += bias[ncol]; v1 += bias[ncol + 1]; }
                if (ACT == 1) { v0 = fmaxf(v0, 0.f); v1 = fmaxf(v1, 0.f); }
                if (ACT == 2) {
                    float u = v0;
                    v0 = 0.5f * u * (1.f + tanhf(0.7978845608028654f * (u + 0.044715f * u * u * u)));
                    u = v1;
                    v1 = 0.5f * u * (1.f + tanhf(0.7978845608028654f * (u + 0.044715f * u * u * u)));
                }
                long long off = (long long)m * ldc + ncol;
                if (res) {
                    float2 r2 = *(const float2*)(res + off);
                    v0 += r2.x; v1 += r2.y;
                }
                float2 o2 = {v0, v1};
                *(float2*)(C + off) = o2;
            }
        }
    }
}

// ---- row L2 normalize: hn = h / (||h|| + 1e-8) ----
__global__ void l2norm_k(const float* __restrict__ h)
{
    int row = blockIdx.x, t = threadIdx.x;
    const float* x = h + (long long)row * EMB;
    __shared__ float red[256];
    float s = 0.f;
    for (int i = t; i < EMB; i += 256) { float v = x[i]; s += v * v; }
    red[t] = s; __syncthreads();
    for (int st = 128; st > 0; st >>= 1) { if (t < st) red[t] += red[t + st]; __syncthreads(); }
    float inv = 1.f / (sqrtf(red[0]) + 1e-8f);
    for (int i = t; i < EMB; i += 256) g_hn[(long long)row * EMB + i] = x[i] * inv;
}

// ---- layernorm (two-pass; eps 1e-6) ----
__global__ void ln_k(const float* __restrict__ x, float* __restrict__ o,
                     const float* __restrict__ gma, const float* __restrict__ bta, int D)
{
    int row = blockIdx.x, t = threadIdx.x;
    const float* xr = x + (long long)row * D;
    __shared__ float red[256];
    __shared__ float s_mu, s_ri;
    float s = 0.f;
    for (int i = t; i < D; i += 256) s += xr[i];
    red[t] = s; __syncthreads();
    for (int st = 128; st > 0; st >>= 1) { if (t < st) red[t] += red[t + st]; __syncthreads(); }
    if (t == 0) s_mu = red[0] / D;
    __syncthreads();
    float mu = s_mu;
    float v = 0.f;
    for (int i = t; i < D; i += 256) { float d = xr[i] - mu; v += d * d; }
    __syncthreads();
    red[t] = v; __syncthreads();
    for (int st = 128; st > 0; st >>= 1) { if (t < st) red[t] += red[t + st]; __syncthreads(); }
    if (t == 0) s_ri = rsqrtf(red[0] / D + 1e-6f);
    __syncthreads();
    float ri = s_ri;
    for (int i = t; i < D; i += 256)
        o[(long long)row * D + i] = (xr[i] - mu) * ri * gma[i] + bta[i];
}

// ---- k-NN: 16 iterated argmins over a shared-memory distance row ----
__global__ void knn_k()
{
    int row = blockIdx.x;             // global row b*S+i
    int b = row / SEQ, i = row % SEQ;
    const float* dr = g_scores + (long long)row * SEQ; // dot products [b][i][j]
    __shared__ float sd[SEQ];
    __shared__ float rv[256];
    __shared__ int   ri[256];
    __shared__ float knd[KNN];
    __shared__ int   sel[KNN];
    int t = threadIdx.x;
    for (int j = t; j < SEQ; j += 256)
        sd[j] = (j == i) ? 1e9f : (1.f - dr[j]);
    __syncthreads();
    for (int it = 0; it < KNN; it++) {
        float bv = 1e30f; int bi = 0x7fffffff;
        for (int j = t; j < SEQ; j += 256) {
            float d = sd[j];
            if (d < bv || (d == bv && j < bi)) { bv = d; bi = j; }
        }
        rv[t] = bv; ri[t] = bi; __syncthreads();
        for (int st = 128; st > 0; st >>= 1) {
            if (t < st) {
                float ov = rv[t + st]; int oi = ri[t + st];
                if (ov < rv[t] || (ov == rv[t] && oi < ri[t])) { rv[t] = ov; ri[t] = oi; }
            }
            __syncthreads();
        }
        if (t == 0) { knd[it] = rv[0]; sel[it] = ri[0]; sd[ri[0]] = 1e9f; }
        __syncthreads();
    }
    if (t == 0) {
        float w[KNN], sum = 0.f;
        for (int k2 = 0; k2 < KNN; k2++) { w[k2] = expf(knd[0] - knd[k2]); sum += w[k2]; }
        float inv = 1.f / sum;
        for (int k2 = 0; k2 < KNN; k2++) {
            g_knw[row * KNN + k2] = w[k2] * inv;
            g_kni[row * KNN + k2] = b * SEQ + sel[k2];
        }
    }
}

// ---- combined = topo + sum_k w_k * topo[nbr_k] ----
__global__ void combine_k()
{
    int row = blockIdx.x, t = threadIdx.x; // 128 threads
    float acc = g_topo[(long long)row * TT + t];
    #pragma unroll
    for (int k2 = 0; k2 < KNN; k2++)
        acc += g_knw[row * KNN + k2] * g_topo[(long long)g_kni[row * KNN + k2] * TT + t];
    g_comb[(long long)row * TT + t] = acc;
}

// ---- attention softmax over keys (scale 1/8, mask==0 -> -10000) ----
__global__ void attn_softmax_k(const int* __restrict__ mask)
{
    int q = blockIdx.x, z = blockIdx.y;
    int b = z / NH;
    float* row = g_scores + (long long)z * SEQ * SEQ + (long long)q * SEQ;
    const int* mrow = mask + b * SEQ;
    int t = threadIdx.x;
    __shared__ float red[256];
    __shared__ float s_mx, s_sum;
    float mx = -1e30f;
    for (int k2 = t; k2 < SEQ; k2 += 256) {
        float v = row[k2] * 0.125f;
        if (mrow[k2] == 0) v = -10000.f;
        row[k2] = v;
        mx = fmaxf(mx, v);
    }
    red[t] = mx; __syncthreads();
    for (int st = 128; st > 0; st >>= 1) { if (t < st) red[t] = fmaxf(red[t], red[t + st]); __syncthreads(); }
    if (t == 0) s_mx = red[0];
    __syncthreads();
    mx = s_mx;
    float sum = 0.f;
    for (int k2 = t; k2 < SEQ; k2 += 256) sum += expf(row[k2] - mx);
    __syncthreads();
    red[t] = sum; __syncthreads();
    for (int st = 128; st > 0; st >>= 1) { if (t < st) red[t] += red[t + st]; __syncthreads(); }
    if (t == 0) s_sum = red[0];
    __syncthreads();
    float inv = 1.f / s_sum;
    for (int k2 = t; k2 < SEQ; k2 += 256) row[k2] = expf(row[k2] - mx) * inv;
}

// ---- concat [ctx, pf] -> cat ----
__global__ void concat_k()
{
    long long idx = (long long)blockIdx.x * 256 + threadIdx.x;
    if (idx >= (long long)BSX * (EMB + TT)) return;
    int row = (int)(idx / (EMB + TT));
    int c   = (int)(idx % (EMB + TT));
    g_cat[idx] = (c < EMB) ? g_ctx[(long long)row * EMB + c]
                           : g_pf[(long long)row * TT + (c - EMB)];
}

// ---- gate = sigmoid(gl); ctx = gate*ctx + (1-gate)*x ----
__global__ void gatemix_k()
{
    long long idx = (long long)blockIdx.x * 256 + threadIdx.x;
    if (idx >= (long long)BSX * EMB) return;
    float g = 1.f / (1.f + expf(-g_gl[idx]));
    g_ctx[idx] = g * g_ctx[idx] + (1.f - g) * g_x[idx];
}

// ============================================================================
extern "C" void kernel_launch(void* const* d_in, const int* in_sizes, int n_in,
                              void* d_out, int out_size)
{
    const float* h      = (const float*)d_in[0];
    const int*   mask   = (const int*)  d_in[1];
    const float* W_topo = (const float*)d_in[2];
    const float* b_topo = (const float*)d_in[3];
    const float* W_m1   = (const float*)d_in[4];
    const float* b_m1   = (const float*)d_in[5];
    const float* W_m2   = (const float*)d_in[6];
    const float* b_m2   = (const float*)d_in[7];
    const float* ln_t_s = (const float*)d_in[8];
    const float* ln_t_b = (const float*)d_in[9];
    const float* W_p1   = (const float*)d_in[10];
    const float* b_p1   = (const float*)d_in[11];
    const float* W_p2   = (const float*)d_in[12];
    const float* b_p2   = (const float*)d_in[13];
    const float* ln1_s  = (const float*)d_in[14];
    const float* ln1_b  = (const float*)d_in[15];
    const float* Wq     = (const float*)d_in[16];
    const float* Wk     = (const float*)d_in[17];
    const float* Wv     = (const float*)d_in[18];
    const float* W_gate = (const float*)d_in[19];
    const float* b_gate = (const float*)d_in[20];
    const float* W_o    = (const float*)d_in[21];
    const float* b_o    = (const float*)d_in[22];
    const float* ln2_s  = (const float*)d_in[23];
    const float* ln2_b  = (const float*)d_in[24];
    const float* W_f1   = (const float*)d_in[25];
    const float* b_f1   = (const float*)d_in[26];
    const float* W_f2   = (const float*)d_in[27];
    const float* b_f2   = (const float*)d_in[28];
    float* out = (float*)d_out;

    float *hn, *x, *topo, *comb, *tmp256, *tt, *pf, *q, *k, *v, *ctx, *cat, *gl, *h1, *y, *ff, *scores;
    cudaGetSymbolAddress((void**)&hn,     g_hn);
    cudaGetSymbolAddress((void**)&x,      g_x);
    cudaGetSymbolAddress((void**)&topo,   g_topo);
    cudaGetSymbolAddress((void**)&comb,   g_comb);
    cudaGetSymbolAddress((void**)&tmp256, g_tmp256);
    cudaGetSymbolAddress((void**)&tt,     g_t);
    cudaGetSymbolAddress((void**)&pf,     g_pf);
    cudaGetSymbolAddress((void**)&q,      g_q);
    cudaGetSymbolAddress((void**)&k,      g_k);
    cudaGetSymbolAddress((void**)&v,      g_v);
    cudaGetSymbolAddress((void**)&ctx,    g_ctx);
    cudaGetSymbolAddress((void**)&cat,    g_cat);
    cudaGetSymbolAddress((void**)&gl,     g_gl);
    cudaGetSymbolAddress((void**)&h1,     g_h1);
    cudaGetSymbolAddress((void**)&y,      g_y);
    cudaGetSymbolAddress((void**)&ff,     g_ff);
    cudaGetSymbolAddress((void**)&scores, g_scores);

    const long long SE  = (long long)SEQ * EMB;
    const long long SS  = (long long)SEQ * SEQ;
    const long long HSS = (long long)NH * SS;

    // 1. hn = normalize(h); x = LN1(h)
    l2norm_k<<<BSX, 256>>>(h);
    ln_k<<<BSX, 256>>>(h, x, ln1_s, ln1_b, EMB);

    // 2. topo = h @ W_topo + b_topo
    tgemm<0, 0, 128><<<dim3(TT / 128, BSX / 128, 1), 256>>>(h, W_topo, topo, b_topo, nullptr,
        BSX, TT, EMB, EMB, TT, TT, 1, 0, 0, 0, 0, 0, 0);

    // 3. dot[b] = hn[b] @ hn[b]^T
    tgemm<1, 0, 128><<<dim3(SEQ / 128, SEQ / 128, 2), 256>>>(hn, hn, scores, nullptr, nullptr,
        SEQ, SEQ, EMB, EMB, EMB, SEQ, 2, SE, 0, SE, 0, SS, 0);

    // 4. per-row top-16 NN + softmax weights; combine
    knn_k<<<BSX, 256>>>();
    combine_k<<<BSX, TT>>>();

    // 5. topo MLP: relu(comb @ W_m1 + b_m1) @ W_m2 + b_m2 ; LN_t
    tgemm<0, 1, 128><<<dim3(256 / 128, BSX / 128, 1), 256>>>(comb, W_m1, tmp256, b_m1, nullptr,
        BSX, 256, TT, TT, 256, 256, 1, 0, 0, 0, 0, 0, 0);
    tgemm<0, 0, 128><<<dim3(TT / 128, BSX / 128, 1), 256>>>(tmp256, W_m2, tt, b_m2, nullptr,
        BSX, TT, 256, 256, TT, TT, 1, 0, 0, 0, 0, 0, 0);
    ln_k<<<BSX, 256>>>(tt, tt, ln_t_s, ln_t_b, TT);

    // 6. pf = relu(t @ W_p1 + b_p1) @ W_p2 + b_p2
    tgemm<0, 1, 128><<<dim3(TT / 128, BSX / 128, 1), 256>>>(tt, W_p1, tmp256, b_p1, nullptr,
        BSX, TT, TT, TT, TT, TT, 1, 0, 0, 0, 0, 0, 0);
    tgemm<0, 0, 128><<<dim3(TT / 128, BSX / 128, 1), 256>>>(tmp256, W_p2, pf, b_p2, nullptr,
        BSX, TT, TT, TT, TT, TT, 1, 0, 0, 0, 0, 0, 0);

    // 7. q/k/v = x @ W{q,k,v}
    tgemm<0, 0, 128><<<dim3(EMB / 128, BSX / 128, 1), 256>>>(x, Wq, q, nullptr, nullptr,
        BSX, EMB, EMB, EMB, EMB, EMB, 1, 0, 0, 0, 0, 0, 0);
    tgemm<0, 0, 128><<<dim3(EMB / 128, BSX / 128, 1), 256>>>(x, Wk, k, nullptr, nullptr,
        BSX, EMB, EMB, EMB, EMB, EMB, 1, 0, 0, 0, 0, 0, 0);
    tgemm<0, 0, 128><<<dim3(EMB / 128, BSX / 128, 1), 256>>>(x, Wv, v, nullptr, nullptr,
        BSX, EMB, EMB, EMB, EMB, EMB, 1, 0, 0, 0, 0, 0, 0);

    // 8. scores[b,h] = q[b,:,h] @ k[b,:,h]^T   (z = b*12 + h)
    tgemm<1, 0, 128><<<dim3(SEQ / 128, SEQ / 128, BB * NH), 256>>>(q, k, scores, nullptr, nullptr,
        SEQ, SEQ, DHD, EMB, EMB, SEQ,
        NH, DHD, SE, DHD, SE, SS, HSS);

    // 9. softmax (scale + mask folded in)
    attn_softmax_k<<<dim3(SEQ, BB * NH), 256>>>(mask);

    // 10. ctx[b,:,h] = probs[b,h] @ v[b,:,h]
    tgemm<0, 0, 64><<<dim3(DHD / 64, SEQ / 128, BB * NH), 256>>>(scores, v, ctx, nullptr, nullptr,
        SEQ, DHD, SEQ, SEQ, EMB, EMB,
        NH, SS, HSS, DHD, SE, DHD, SE);

    // 11. gate = sigmoid([ctx, pf] @ W_gate + b_gate); ctx = gate*ctx + (1-gate)*x
    {
        long long n = (long long)BSX * (EMB + TT);
        concat_k<<<(unsigned)((n + 255) / 256), 256>>>();
    }
    tgemm<0, 0, 128><<<dim3(EMB / 128, BSX / 128, 1), 256>>>(cat, W_gate, gl, b_gate, nullptr,
        BSX, EMB, EMB + TT, EMB + TT, EMB, EMB, 1, 0, 0, 0, 0, 0, 0);
    {
        long long n = (long long)BSX * EMB;
        gatemix_k<<<(unsigned)((n + 255) / 256), 256>>>();
    }

    // 12. h1 = h + ctx @ W_o + b_o
    tgemm<0, 0, 128><<<dim3(EMB / 128, BSX / 128, 1), 256>>>(ctx, W_o, h1, b_o, h,
        BSX, EMB, EMB, EMB, EMB, EMB, 1, 0, 0, 0, 0, 0, 0);

    // 13. FFN: y = LN2(h1); out = h1 + gelu(y@W_f1+b_f1) @ W_f2 + b_f2
    ln_k<<<BSX, 256>>>(h1, y, ln2_s, ln2_b, EMB);
    tgemm<0, 2, 128><<<dim3(FF / 128, BSX / 128, 1), 256>>>(y, W_f1, ff, b_f1, nullptr,
        BSX, FF, EMB, EMB, FF, FF, 1, 0, 0, 0, 0, 0, 0);
    tgemm<0, 0, 128><<<dim3(EMB / 128, BSX / 128, 1), 256>>>(ff, W_f2, out, b_f2, h1,
        BSX, EMB, FF, FF, EMB, EMB, 1, 0, 0, 0, 0, 0, 0);
}

// round 3
// speedup vs baseline: 2.7808x; 1.2224x over previous
#include <cuda_runtime.h>
#include <math.h>
#include <stdint.h>

// ---- problem constants ----
#define BSX 4096   // B*S
#define BB  2
#define SEQ 2048
#define EMB 768
#define TT  128
#define NH  12
#define DHD 64
#define FF  3072
#define KNN 16
#define CATW (EMB + TT)   // 896

// ---- scratch (device globals) ----
__device__ float g_hn[BSX * EMB];
__device__ float g_x[BSX * EMB];
__device__ float g_topo[BSX * TT];
__device__ float g_comb[BSX * TT];
__device__ float g_tmp256[BSX * 256];
__device__ float g_t[BSX * TT];
__device__ float g_q[BSX * EMB];
__device__ float g_k[BSX * EMB];
__device__ float g_v[BSX * EMB];
__device__ float g_ctx[BSX * EMB];
__device__ float g_cat[BSX * CATW];
__device__ float g_h1[BSX * EMB];
__device__ float g_y[BSX * EMB];
__device__ float g_ff[(long long)BSX * FF];
__device__ float g_knw[BSX * KNN];
__device__ int   g_kni[BSX * KNN];
__device__ float g_scores[(long long)BB * NH * SEQ * SEQ];

__device__ __forceinline__ void mma_tf32(float* c, const uint32_t* a, uint32_t b0, uint32_t b1) {
    asm volatile(
        "mma.sync.aligned.m16n8k8.row.col.f32.tf32.tf32.f32 "
        "{%0,%1,%2,%3},{%4,%5,%6,%7},{%8,%9},{%0,%1,%2,%3};"
        : "+f"(c[0]), "+f"(c[1]), "+f"(c[2]), "+f"(c[3])
        : "r"(a[0]), "r"(a[1]), "r"(a[2]), "r"(a[3]), "r"(b0), "r"(b1));
}

__device__ __forceinline__ void cpa16(void* s, const void* g) {
    unsigned sa = (unsigned)__cvta_generic_to_shared(s);
    asm volatile("cp.async.cg.shared.global [%0], [%1], 16;" :: "r"(sa), "l"(g));
}
__device__ __forceinline__ void cpa_commit() { asm volatile("cp.async.commit_group;"); }
__device__ __forceinline__ void cpa_wait2()  { asm volatile("cp.async.wait_group 2;"); }

// ============================================================================
// tf32 tensor-core GEMM, cp.async 3-stage pipeline. Block tile 128 x TN,
// 256 threads, 8 warps (warp tile 32 x TN/2). Raw fp32 bits used as tf32
// (hardware truncation). ACT: 0 none, 1 relu, 2 gelu, 3 sigmoid-mix
// (C = s*res + (1-s)*res2, s = sigmoid(acc+bias)); ACT!=3 & res: C += res.
// Requirements: M%128==0, N%TN==0, K%16==0, TN in {64,128}.
// ============================================================================
template<int TRANSB, int ACT, int TN>
__global__ void __launch_bounds__(256) tgemm(
    const float* __restrict__ A, const float* __restrict__ B,
    float* __restrict__ C, const float* __restrict__ bias,
    const float* __restrict__ res, const float* __restrict__ res2,
    int K, int lda, int ldb, int ldc, int ldr1, int ldr2,
    int zdiv, long long sA1, long long sA2,
    long long sB1, long long sB2, long long sC1, long long sC2)
{
    constexpr int NT    = TN / 16;
    constexpr int BITER = TN / 64;          // B chunks per thread per stage
    constexpr int BCOLS = TRANSB ? 20 : (TN + 8);

    extern __shared__ uint32_t sm[];
    uint32_t* As = sm;                      // [3][128][20]
    uint32_t* Bs = sm + 3 * 128 * 20;       // [3][BROWS][BCOLS]

    int z = blockIdx.z;
    long long zm = z % zdiv, zd = z / zdiv;
    A += zm * sA1 + zd * sA2;
    B += zm * sB1 + zd * sB2;
    long long co = zm * sC1 + zd * sC2;
    C += co;

    const int t    = threadIdx.x;
    const int lane = t & 31;
    const int wid  = t >> 5;
    const int lr   = lane >> 2;
    const int lc   = lane & 3;
    const int wm   = (wid & 3) * 32;
    const int wn   = (wid >> 2) * (TN / 2);
    const int bm   = blockIdx.y * 128;
    const int bn   = blockIdx.x * TN;

    float acc[2][NT][4];
    #pragma unroll
    for (int mt = 0; mt < 2; mt++)
        #pragma unroll
        for (int nt = 0; nt < NT; nt++)
            #pragma unroll
            for (int i = 0; i < 4; i++) acc[mt][nt][i] = 0.f;

    auto issue = [&](int buf, int k0) {
        #pragma unroll
        for (int i = 0; i < 2; i++) {
            int c = t + i * 256;
            int row = c >> 2, kq = (c & 3) << 2;
            cpa16(&As[((buf << 7) + row) * 20 + kq],
                  A + (long long)(bm + row) * lda + k0 + kq);
        }
        if (TRANSB) {
            #pragma unroll
            for (int i = 0; i < BITER; i++) {
                int c = t + i * 256;
                int row = c >> 2, kq = (c & 3) << 2;
                cpa16(&Bs[(buf * TN + row) * 20 + kq],
                      B + (long long)(bn + row) * ldb + k0 + kq);
            }
        } else {
            #pragma unroll
            for (int i = 0; i < BITER; i++) {
                int c = t + i * 256;
                int krow = c / (TN / 4), n4 = (c % (TN / 4)) << 2;
                cpa16(&Bs[(buf * 16 + krow) * BCOLS + n4],
                      B + (long long)(k0 + krow) * ldb + bn + n4);
            }
        }
        cpa_commit();
    };

    const int iters = K >> 4;
    issue(0, 0);
    issue(1, 16);

    for (int kb = 0; kb < iters; kb++) {
        int nst  = kb + 2;
        int nbuf = nst - (nst / 3) * 3;
        int nk0  = (nst < iters ? nst : iters - 1) << 4;
        issue(nbuf, nk0);
        cpa_wait2();
        __syncthreads();
        int cur = kb - (kb / 3) * 3;

        #pragma unroll
        for (int ks = 0; ks < 16; ks += 8) {
            uint32_t af[2][4];
            #pragma unroll
            for (int mt = 0; mt < 2; mt++) {
                int m = (cur << 7) + wm + mt * 16 + lr;
                af[mt][0] = As[m * 20 + ks + lc];
                af[mt][1] = As[(m + 8) * 20 + ks + lc];
                af[mt][2] = As[m * 20 + ks + lc + 4];
                af[mt][3] = As[(m + 8) * 20 + ks + lc + 4];
            }
            #pragma unroll
            for (int nt = 0; nt < NT; nt++) {
                int n = wn + nt * 8 + lr;
                uint32_t b0, b1;
                if (TRANSB) {
                    b0 = Bs[(cur * TN + n) * 20 + ks + lc];
                    b1 = Bs[(cur * TN + n) * 20 + ks + lc + 4];
                } else {
                    b0 = Bs[(cur * 16 + ks + lc) * BCOLS + n];
                    b1 = Bs[(cur * 16 + ks + lc + 4) * BCOLS + n];
                }
                #pragma unroll
                for (int mt = 0; mt < 2; mt++)
                    mma_tf32(acc[mt][nt], af[mt], b0, b1);
            }
        }
        __syncthreads();
    }

    // epilogue
    #pragma unroll
    for (int mt = 0; mt < 2; mt++) {
        #pragma unroll
        for (int nt = 0; nt < NT; nt++) {
            int mrow = bm + wm + mt * 16 + lr;
            int ncol = bn + wn + nt * 8 + 2 * lc;
            #pragma unroll
            for (int half = 0; half < 2; half++) {
                int m = mrow + half * 8;
                float v0 = acc[mt][nt][half * 2 + 0];
                float v1 = acc[mt][nt][half * 2 + 1];
                if (bias) { v0 += bias[ncol]; v1 += bias[ncol + 1]; }
                if (ACT == 1) { v0 = fmaxf(v0, 0.f); v1 = fmaxf(v1, 0.f); }
                if (ACT == 2) {
                    float u = v0;
                    v0 = 0.5f * u * (1.f + tanhf(0.7978845608028654f * (u + 0.044715f * u * u * u)));
                    u = v1;
                    v1 = 0.5f * u * (1.f + tanhf(0.7978845608028654f * (u + 0.044715f * u * u * u)));
                }
                long long off = (long long)m * ldc + ncol;
                if (ACT == 3) {
                    float s0 = 1.f / (1.f + expf(-v0));
                    float s1 = 1.f / (1.f + expf(-v1));
                    long long o1 = (long long)m * ldr1 + ncol;
                    long long o2 = (long long)m * ldr2 + ncol;
                    float2 r1 = *(const float2*)(res + o1);
                    float2 r2 = *(const float2*)(res2 + o2);
                    v0 = s0 * r1.x + (1.f - s0) * r2.x;
                    v1 = s1 * r1.y + (1.f - s1) * r2.y;
                } else if (res) {
                    float2 r1 = *(const float2*)(res + (long long)m * ldr1 + ncol);
                    v0 += r1.x; v1 += r1.y;
                }
                float2 o2v = {v0, v1};
                *(float2*)(C + off) = o2v;
            }
        }
    }
}

// ---- fused: hn = h/(||h||+1e-8) ; x = LN1(h) ----
__global__ void l2ln_k(const float* __restrict__ h,
                       const float* __restrict__ gma, const float* __restrict__ bta)
{
    int row = blockIdx.x, t = threadIdx.x;
    const float* xr = h + (long long)row * EMB;
    __shared__ float sh[EMB];
    __shared__ float r1[256], r2[256];
    float s = 0.f, ss = 0.f;
    for (int i = t; i < EMB; i += 256) { float v = xr[i]; sh[i] = v; s += v; ss += v * v; }
    r1[t] = s; r2[t] = ss; __syncthreads();
    for (int st = 128; st > 0; st >>= 1) {
        if (t < st) { r1[t] += r1[t + st]; r2[t] += r2[t + st]; }
        __syncthreads();
    }
    float mu   = r1[0] / EMB;
    float var  = r2[0] / EMB - mu * mu;
    float ri   = rsqrtf(var + 1e-6f);
    float invn = 1.f / (sqrtf(r2[0]) + 1e-8f);
    for (int i = t; i < EMB; i += 256) {
        float v = sh[i];
        g_hn[(long long)row * EMB + i] = v * invn;
        g_x [(long long)row * EMB + i] = (v - mu) * ri * gma[i] + bta[i];
    }
}

// ---- layernorm (two-pass; eps 1e-6) ----
__global__ void ln_k(const float* __restrict__ x, float* __restrict__ o,
                     const float* __restrict__ gma, const float* __restrict__ bta, int D)
{
    int row = blockIdx.x, t = threadIdx.x;
    const float* xr = x + (long long)row * D;
    __shared__ float red[256];
    __shared__ float s_mu, s_ri;
    float s = 0.f;
    for (int i = t; i < D; i += 256) s += xr[i];
    red[t] = s; __syncthreads();
    for (int st = 128; st > 0; st >>= 1) { if (t < st) red[t] += red[t + st]; __syncthreads(); }
    if (t == 0) s_mu = red[0] / D;
    __syncthreads();
    float mu = s_mu;
    float v = 0.f;
    for (int i = t; i < D; i += 256) { float d = xr[i] - mu; v += d * d; }
    __syncthreads();
    red[t] = v; __syncthreads();
    for (int st = 128; st > 0; st >>= 1) { if (t < st) red[t] += red[t + st]; __syncthreads(); }
    if (t == 0) s_ri = rsqrtf(red[0] / D + 1e-6f);
    __syncthreads();
    float ri = s_ri;
    for (int i = t; i < D; i += 256)
        o[(long long)row * D + i] = (xr[i] - mu) * ri * gma[i] + bta[i];
}

// ---- k-NN: 16 iterated argmins over shared-memory distance row ----
__global__ void knn_k()
{
    int row = blockIdx.x;
    int b = row / SEQ, i = row % SEQ;
    const float* dr = g_scores + (long long)row * SEQ;
    __shared__ float sd[SEQ];
    __shared__ float rv[256];
    __shared__ int   ri[256];
    __shared__ float knd[KNN];
    __shared__ int   sel[KNN];
    int t = threadIdx.x;
    for (int j = t; j < SEQ; j += 256)
        sd[j] = (j == i) ? 1e9f : (1.f - dr[j]);
    __syncthreads();
    for (int it = 0; it < KNN; it++) {
        float bv = 1e30f; int bi = 0x7fffffff;
        for (int j = t; j < SEQ; j += 256) {
            float d = sd[j];
            if (d < bv || (d == bv && j < bi)) { bv = d; bi = j; }
        }
        rv[t] = bv; ri[t] = bi; __syncthreads();
        for (int st = 128; st > 0; st >>= 1) {
            if (t < st) {
                float ov = rv[t + st]; int oi = ri[t + st];
                if (ov < rv[t] || (ov == rv[t] && oi < ri[t])) { rv[t] = ov; ri[t] = oi; }
            }
            __syncthreads();
        }
        if (t == 0) { knd[it] = rv[0]; sel[it] = ri[0]; sd[ri[0]] = 1e9f; }
        __syncthreads();
    }
    if (t == 0) {
        float w[KNN], sum = 0.f;
        for (int k2 = 0; k2 < KNN; k2++) { w[k2] = expf(knd[0] - knd[k2]); sum += w[k2]; }
        float inv = 1.f / sum;
        for (int k2 = 0; k2 < KNN; k2++) {
            g_knw[row * KNN + k2] = w[k2] * inv;
            g_kni[row * KNN + k2] = b * SEQ + sel[k2];
        }
    }
}

// ---- combined = topo + sum_k w_k * topo[nbr_k] ----
__global__ void combine_k()
{
    int row = blockIdx.x, t = threadIdx.x; // 128 threads
    float acc = g_topo[(long long)row * TT + t];
    #pragma unroll
    for (int k2 = 0; k2 < KNN; k2++)
        acc += g_knw[row * KNN + k2] * g_topo[(long long)g_kni[row * KNN + k2] * TT + t];
    g_comb[(long long)row * TT + t] = acc;
}

// ---- attention softmax: row in registers, 1R + 1W ----
__global__ void attn_softmax_k(const int* __restrict__ mask)
{
    int q = blockIdx.x, z = blockIdx.y, b = z / NH;
    float* row = g_scores + (long long)z * SEQ * SEQ + (long long)q * SEQ;
    const int* mrow = mask + b * SEQ;
    int t = threadIdx.x;
    __shared__ float red[256];
    float vals[8];
    float mx = -1e30f;
    #pragma unroll
    for (int i = 0; i < 8; i++) {
        int k2 = t + i * 256;
        float v = row[k2] * 0.125f;
        if (mrow[k2] == 0) v = -10000.f;
        vals[i] = v; mx = fmaxf(mx, v);
    }
    red[t] = mx; __syncthreads();
    for (int st = 128; st > 0; st >>= 1) { if (t < st) red[t] = fmaxf(red[t], red[t + st]); __syncthreads(); }
    mx = red[0];
    __syncthreads();
    float sum = 0.f;
    #pragma unroll
    for (int i = 0; i < 8; i++) { vals[i] = expf(vals[i] - mx); sum += vals[i]; }
    red[t] = sum; __syncthreads();
    for (int st = 128; st > 0; st >>= 1) { if (t < st) red[t] += red[t + st]; __syncthreads(); }
    float inv = 1.f / red[0];
    #pragma unroll
    for (int i = 0; i < 8; i++) row[t + i * 256] = vals[i] * inv;
}

// ============================================================================
template<int TRANSB, int TN>
static int smem_bytes() {
    int a = 3 * 128 * 20 * 4;
    int b = TRANSB ? 3 * TN * 20 * 4 : 3 * 16 * (TN + 8) * 4;
    return a + b;
}

extern "C" void kernel_launch(void* const* d_in, const int* in_sizes, int n_in,
                              void* d_out, int out_size)
{
    const float* h      = (const float*)d_in[0];
    const int*   mask   = (const int*)  d_in[1];
    const float* W_topo = (const float*)d_in[2];
    const float* b_topo = (const float*)d_in[3];
    const float* W_m1   = (const float*)d_in[4];
    const float* b_m1   = (const float*)d_in[5];
    const float* W_m2   = (const float*)d_in[6];
    const float* b_m2   = (const float*)d_in[7];
    const float* ln_t_s = (const float*)d_in[8];
    const float* ln_t_b = (const float*)d_in[9];
    const float* W_p1   = (const float*)d_in[10];
    const float* b_p1   = (const float*)d_in[11];
    const float* W_p2   = (const float*)d_in[12];
    const float* b_p2   = (const float*)d_in[13];
    const float* ln1_s  = (const float*)d_in[14];
    const float* ln1_b  = (const float*)d_in[15];
    const float* Wq     = (const float*)d_in[16];
    const float* Wk     = (const float*)d_in[17];
    const float* Wv     = (const float*)d_in[18];
    const float* W_gate = (const float*)d_in[19];
    const float* b_gate = (const float*)d_in[20];
    const float* W_o    = (const float*)d_in[21];
    const float* b_o    = (const float*)d_in[22];
    const float* ln2_s  = (const float*)d_in[23];
    const float* ln2_b  = (const float*)d_in[24];
    const float* W_f1   = (const float*)d_in[25];
    const float* b_f1   = (const float*)d_in[26];
    const float* W_f2   = (const float*)d_in[27];
    const float* b_f2   = (const float*)d_in[28];
    float* out = (float*)d_out;

    float *hn, *x, *topo, *comb, *tmp256, *tt, *q, *k, *v, *ctx, *cat, *h1, *y, *ff, *scores;
    cudaGetSymbolAddress((void**)&hn,     g_hn);
    cudaGetSymbolAddress((void**)&x,      g_x);
    cudaGetSymbolAddress((void**)&topo,   g_topo);
    cudaGetSymbolAddress((void**)&comb,   g_comb);
    cudaGetSymbolAddress((void**)&tmp256, g_tmp256);
    cudaGetSymbolAddress((void**)&tt,     g_t);
    cudaGetSymbolAddress((void**)&q,      g_q);
    cudaGetSymbolAddress((void**)&k,      g_k);
    cudaGetSymbolAddress((void**)&v,      g_v);
    cudaGetSymbolAddress((void**)&ctx,    g_ctx);
    cudaGetSymbolAddress((void**)&cat,    g_cat);
    cudaGetSymbolAddress((void**)&h1,     g_h1);
    cudaGetSymbolAddress((void**)&y,      g_y);
    cudaGetSymbolAddress((void**)&ff,     g_ff);
    cudaGetSymbolAddress((void**)&scores, g_scores);

    const long long SE  = (long long)SEQ * EMB;
    const long long SS  = (long long)SEQ * SEQ;
    const long long HSS = (long long)NH * SS;

    const int sm_nn128 = smem_bytes<0, 128>();
    const int sm_tb128 = smem_bytes<1, 128>();
    const int sm_nn64  = smem_bytes<0, 64>();
    cudaFuncSetAttribute((const void*)tgemm<0, 0, 128>, cudaFuncAttributeMaxDynamicSharedMemorySize, sm_nn128);
    cudaFuncSetAttribute((const void*)tgemm<0, 1, 128>, cudaFuncAttributeMaxDynamicSharedMemorySize, sm_nn128);
    cudaFuncSetAttribute((const void*)tgemm<0, 2, 128>, cudaFuncAttributeMaxDynamicSharedMemorySize, sm_nn128);
    cudaFuncSetAttribute((const void*)tgemm<0, 3, 128>, cudaFuncAttributeMaxDynamicSharedMemorySize, sm_nn128);
    cudaFuncSetAttribute((const void*)tgemm<1, 0, 128>, cudaFuncAttributeMaxDynamicSharedMemorySize, sm_tb128);
    cudaFuncSetAttribute((const void*)tgemm<0, 0, 64>,  cudaFuncAttributeMaxDynamicSharedMemorySize, sm_nn64);

    // 1. hn = normalize(h); x = LN1(h)   (fused)
    l2ln_k<<<BSX, 256>>>(h, ln1_s, ln1_b);

    // 2. topo = h @ W_topo + b_topo
    tgemm<0, 0, 128><<<dim3(1, 32, 1), 256, sm_nn128>>>(h, W_topo, topo, b_topo, nullptr, nullptr,
        EMB, EMB, TT, TT, 0, 0, 1, 0, 0, 0, 0, 0, 0);

    // 3. dot[b] = hn[b] @ hn[b]^T
    tgemm<1, 0, 128><<<dim3(16, 16, 2), 256, sm_tb128>>>(hn, hn, scores, nullptr, nullptr, nullptr,
        EMB, EMB, EMB, SEQ, 0, 0, 2, SE, 0, SE, 0, SS, 0);

    // 4. per-row top-16 NN + weights; combine
    knn_k<<<BSX, 256>>>();
    combine_k<<<BSX, TT>>>();

    // 5. topo MLP + LN_t
    tgemm<0, 1, 128><<<dim3(2, 32, 1), 256, sm_nn128>>>(comb, W_m1, tmp256, b_m1, nullptr, nullptr,
        TT, TT, 256, 256, 0, 0, 1, 0, 0, 0, 0, 0, 0);
    tgemm<0, 0, 128><<<dim3(1, 32, 1), 256, sm_nn128>>>(tmp256, W_m2, tt, b_m2, nullptr, nullptr,
        256, 256, TT, TT, 0, 0, 1, 0, 0, 0, 0, 0, 0);
    ln_k<<<BSX, 256>>>(tt, tt, ln_t_s, ln_t_b, TT);

    // 6. pf = relu(t@W_p1+b_p1)@W_p2+b_p2  -> written into cat[:, EMB:]
    tgemm<0, 1, 128><<<dim3(1, 32, 1), 256, sm_nn128>>>(tt, W_p1, tmp256, b_p1, nullptr, nullptr,
        TT, TT, TT, TT, 0, 0, 1, 0, 0, 0, 0, 0, 0);
    tgemm<0, 0, 128><<<dim3(1, 32, 1), 256, sm_nn128>>>(tmp256, W_p2, cat + EMB, b_p2, nullptr, nullptr,
        TT, TT, TT, CATW, 0, 0, 1, 0, 0, 0, 0, 0, 0);

    // 7. q/k/v
    tgemm<0, 0, 128><<<dim3(6, 32, 1), 256, sm_nn128>>>(x, Wq, q, nullptr, nullptr, nullptr,
        EMB, EMB, EMB, EMB, 0, 0, 1, 0, 0, 0, 0, 0, 0);
    tgemm<0, 0, 128><<<dim3(6, 32, 1), 256, sm_nn128>>>(x, Wk, k, nullptr, nullptr, nullptr,
        EMB, EMB, EMB, EMB, 0, 0, 1, 0, 0, 0, 0, 0, 0);
    tgemm<0, 0, 128><<<dim3(6, 32, 1), 256, sm_nn128>>>(x, Wv, v, nullptr, nullptr, nullptr,
        EMB, EMB, EMB, EMB, 0, 0, 1, 0, 0, 0, 0, 0, 0);

    // 8. scores[b,h] = q @ k^T
    tgemm<1, 0, 128><<<dim3(16, 16, BB * NH), 256, sm_tb128>>>(q, k, scores, nullptr, nullptr, nullptr,
        DHD, EMB, EMB, SEQ, 0, 0, NH, DHD, SE, DHD, SE, SS, HSS);

    // 9. softmax
    attn_softmax_k<<<dim3(SEQ, BB * NH), 256>>>(mask);

    // 10. ctx = probs @ v  -> written into cat[:, :EMB] per head
    tgemm<0, 0, 64><<<dim3(1, 16, BB * NH), 256, sm_nn64>>>(scores, v, cat, nullptr, nullptr, nullptr,
        SEQ, SEQ, EMB, CATW, 0, 0, NH, SS, HSS, DHD, SE, DHD, (long long)SEQ * CATW);

    // 11. gate-mix: ctx = sigmoid(cat@W_gate+b_gate)*ctx_cat + (1-s)*x
    tgemm<0, 3, 128><<<dim3(6, 32, 1), 256, sm_nn128>>>(cat, W_gate, ctx, b_gate, cat, x,
        CATW, CATW, EMB, EMB, CATW, EMB, 1, 0, 0, 0, 0, 0, 0);

    // 12. h1 = h + ctx @ W_o + b_o
    tgemm<0, 0, 128><<<dim3(6, 32, 1), 256, sm_nn128>>>(ctx, W_o, h1, b_o, h, nullptr,
        EMB, EMB, EMB, EMB, EMB, 0, 1, 0, 0, 0, 0, 0, 0);

    // 13. FFN
    ln_k<<<BSX, 256>>>(h1, y, ln2_s, ln2_b, EMB);
    tgemm<0, 2, 128><<<dim3(24, 32, 1), 256, sm_nn128>>>(y, W_f1, ff, b_f1, nullptr, nullptr,
        EMB, EMB, FF, FF, 0, 0, 1, 0, 0, 0, 0, 0, 0);
    tgemm<0, 0, 128><<<dim3(6, 32, 1), 256, sm_nn128>>>(ff, W_f2, out, b_f2, h1, nullptr,
        FF, FF, EMB, EMB, EMB, 0, 1, 0, 0, 0, 0, 0, 0);
}